// round 13
// baseline (speedup 1.0000x reference)
#include <cuda_runtime.h>
#include <cuda_bf16.h>

// y[i,a,b] = sum_{kj,kh,l} w[i,kj,kh,l] * U[a+kj-1, kh, b, l]   (zero pad on a+kj-1)
// U[ap,kh,b,l] = T(ap,kh,(b-1)%14, l+128) + T(ap,kh,b,l)
// T(ap,kh,b',c) = (0 <= b'+kh-1 < 14) ? x[c, ap, (b'+kh-2) mod 14] : 0

#define U_ELEMS (14 * 3 * 14 * 128)     // 75264
#define W_ELEMS (256 * 1152)            // 294912
#define U_BLOCKS 294                     // 294*256 == 75264
#define W_BLOCKS 1152                    // 1152*256 == 294912
#define GEMM_SMEM (16128 * 4)            // 64512 B: [b=14][k=1152] floats (>= 57344 red)

__device__ float g_U[U_ELEMS];          // [ap][kh][b][l]
__device__ float g_Wt[W_ELEMS];         // packed: [k/4][i=256][4]  (i-coalesced)

// Fused prep: blocks [0,294) build U; blocks [294,1446) transpose/pack w.
__global__ void prep_kernel(const float* __restrict__ x, const float* __restrict__ w) {
    if (blockIdx.x < U_BLOCKS) {
        int e = blockIdx.x * 256 + threadIdx.x;      // < 75264
        int l  = e & 127;
        int b  = (e >> 7) % 14;
        int kh = (e / (128 * 14)) % 3;
        int ap = e / (128 * 14 * 3);

        float val = 0.0f;
        int t = b + kh - 1;
        if (t >= 0 && t < 14) {
            int wsrc = t - 1; if (wsrc < 0) wsrc += 14;
            val += x[l * 196 + ap * 14 + wsrc];
        }
        int bm = b - 1; if (bm < 0) bm += 14;
        int t1 = bm + kh - 1;
        if (t1 >= 0 && t1 < 14) {
            int wsrc = t1 - 1; if (wsrc < 0) wsrc += 14;
            val += x[(l + 128) * 196 + ap * 14 + wsrc];
        }
        g_U[e] = val;
    } else {
        int e = (blockIdx.x - U_BLOCKS) * 256 + threadIdx.x;  // < 294912, coalesced read
        int i = e / 1152;
        int k = e - i * 1152;
        g_Wt[(k >> 2) * 1024 + i * 4 + (k & 3)] = w[e];
    }
}

// Grid (a=14, i-tile=8), 1024 threads = 32 warps (8/SMSP). lane = channel i0+lane.
// K split over 32 warps (36 k = 9 ulonglong2 chunks each). u_s[b][k-linear]:
// one broadcast LDS.128 = two ready f32x2 pairs; w ulonglong2 = matching pairs.
// FFMA2 body (fewest instrs) + 8 warps/SMSP (latency hiding).
// NOTE: u_s row stride is 288 ulonglong2 (1152 floats) regardless of warp count.
__global__ __launch_bounds__(1024, 1)
void gemm_kernel(float* __restrict__ y) {
    extern __shared__ float u_s[];       // [b=14][k=1152] = 16128 floats; reused as red

    const int a   = blockIdx.x;          // 0..13
    const int i0  = blockIdx.y * 32;
    const int tid = threadIdx.x;

    // ---- stage u_s[b][kj*384+kh*128+l] from g_U rows ap = a-1..a+1 ----
    float4* u4s = (float4*)u_s;
#pragma unroll
    for (int it = 0; it < 4; it++) {
        int idx = it * 1024 + tid;                   // < 4096; valid < 4032
        if (idx < 4032) {
            int b  = idx / 288;                      // 1152/4
            int r  = idx - b * 288;
            int kj = r / 96;
            int r2 = r - kj * 96;                    // kh*32 + l4
            int ap = a - 1 + kj;
            float4 v = make_float4(0.f, 0.f, 0.f, 0.f);
            if (ap >= 0 && ap < 14)
                v = ((const float4*)g_U)[ap * 1344 + (r2 >> 5) * 448 + b * 32 + (r2 & 31)];
            u4s[b * 288 + r] = v;
        }
    }
    __syncthreads();

    const int warp = tid >> 5;           // 0..31
    const int lane = tid & 31;

    unsigned long long acc2[14];
#pragma unroll
    for (int b = 0; b < 14; b++) acc2[b] = 0ull;

    // w: lane reads {k..k+3} of row i0+lane as 2 f32x2 pairs; lanes contiguous.
    const ulonglong2* wp = ((const ulonglong2*)g_Wt) + (warp * 9) * 256 + i0 + lane;
    const ulonglong2* up = ((const ulonglong2*)u_s) + warp * 9;

#pragma unroll 3
    for (int t = 0; t < 9; t++) {
        ulonglong2 wv = wp[t * 256];                 // coalesced LDG.128
#pragma unroll
        for (int b = 0; b < 14; b++) {
            ulonglong2 uv = up[b * 288 + t];         // broadcast LDS.128 = 2 pairs
            asm("fma.rn.f32x2 %0, %1, %2, %0;" : "+l"(acc2[b]) : "l"(wv.x), "l"(uv.x));
            asm("fma.rn.f32x2 %0, %1, %2, %0;" : "+l"(acc2[b]) : "l"(wv.y), "l"(uv.y));
        }
    }

    __syncthreads();                                 // u_s now reusable as red buffer
    float* red = u_s;                                // [warp=32][b=14][lane=32] = 14336
#pragma unroll
    for (int b = 0; b < 14; b++) {
        float lo, hi;
        asm("mov.b64 {%0, %1}, %2;" : "=f"(lo), "=f"(hi) : "l"(acc2[b]));
        red[(warp * 14 + b) * 32 + lane] = lo + hi;
    }
    __syncthreads();

    if (tid < 14 * 32) {
        int b = tid >> 5;
        int i = tid & 31;
        float s = 0.f;
#pragma unroll
        for (int wq = 0; wq < 32; wq++) s += red[(wq * 14 + b) * 32 + i];
        y[(i0 + i) * 196 + a * 14 + b] = s;
    }
}

extern "C" void kernel_launch(void* const* d_in, const int* in_sizes, int n_in,
                              void* d_out, int out_size) {
    const float* x = (const float*)d_in[0];
    const float* w = (const float*)d_in[1];
    float* y = (float*)d_out;

    cudaFuncSetAttribute(gemm_kernel,
                         cudaFuncAttributeMaxDynamicSharedMemorySize, GEMM_SMEM);

    prep_kernel<<<U_BLOCKS + W_BLOCKS, 256>>>(x, w);
    gemm_kernel<<<dim3(14, 8), 1024, GEMM_SMEM>>>(y);
}

// round 14
// speedup vs baseline: 1.0329x; 1.0329x over previous
#include <cuda_runtime.h>
#include <cuda_bf16.h>

// y[i,a,b] = sum_{kj,kh,l} w[i,kj,kh,l] * U[a+kj-1, kh, b, l]   (zero pad on a+kj-1)
// U[ap,kh,b,l] = T(ap,kh,(b-1)%14, l+128) + T(ap,kh,b,l)
// T(ap,kh,b',c) = (0 <= b'+kh-1 < 14) ? x[c, ap, (b'+kh-2) mod 14] : 0

#define U_ELEMS (14 * 3 * 14 * 128)     // 75264
#define W_ELEMS (256 * 1152)            // 294912
#define U_BLOCKS 294                     // 294*256 == 75264
#define W_BLOCKS 1152                    // 1152*256 == 294912
// smem: staging 64512B (u_s[14][1152]) then reduction 224*65*8 = 116480B
#define GEMM_SMEM 116480

__device__ float g_U[U_ELEMS];          // [ap][kh][b][l]
__device__ float g_Wp[W_ELEMS];         // packed per-thread step chunks (see pack below)

// Fused prep: blocks [0,294) build U; blocks [294,1446) pack w.
// Pack target: for w[i][k] with i = G*4+c (G=0..63 channel-quad), and
// k -> s=k/576, j=(k%576)/64, lane=(k%64)/2, t=k&1:
//   g_Wp[ ((((s*9+j)*64 + G)*32 + lane)*8) + t*4 + c ]
// so one thread's step chunk is 8 contiguous floats: [k0: c0..c3 | k1: c0..c3],
// and a warp's 32 chunks are contiguous (coalesced LDG.128 x2 per step).
__global__ void prep_kernel(const float* __restrict__ x, const float* __restrict__ w) {
    if (blockIdx.x < U_BLOCKS) {
        int e = blockIdx.x * 256 + threadIdx.x;      // < 75264
        int l  = e & 127;
        int b  = (e >> 7) % 14;
        int kh = (e / (128 * 14)) % 3;
        int ap = e / (128 * 14 * 3);

        float val = 0.0f;
        int t = b + kh - 1;
        if (t >= 0 && t < 14) {
            int wsrc = t - 1; if (wsrc < 0) wsrc += 14;
            val += x[l * 196 + ap * 14 + wsrc];
        }
        int bm = b - 1; if (bm < 0) bm += 14;
        int t1 = bm + kh - 1;
        if (t1 >= 0 && t1 < 14) {
            int wsrc = t1 - 1; if (wsrc < 0) wsrc += 14;
            val += x[(l + 128) * 196 + ap * 14 + wsrc];
        }
        g_U[e] = val;
    } else {
        int e = (blockIdx.x - U_BLOCKS) * 256 + threadIdx.x;  // < 294912, coalesced read
        int i = e / 1152;
        int k = e - i * 1152;
        int G = i >> 2, c = i & 3;
        int s = k / 576, rem = k - s * 576;
        int j = rem >> 6, rr = rem & 63;
        int lane = rr >> 1, t = rr & 1;
        g_Wp[((((s * 9 + j) * 64 + G) * 32 + lane) << 3) + t * 4 + c] = w[e];
    }
}

// Grid (a=14, i-tile=8), 512 threads = 16 warps = 8 channel-quads x 2 K-slices.
// Warp (g,s): channels i0+g*4+{0..3}, k in [s*576, s*576+576).
// Lane owns k = s*576 + j*64 + lane*2 + {0,1}, j = 0..8.
// Per step: 2 coalesced LDG.128 (w chunk) + 14 conflict-free LDS.64 (u, serves 4 ch)
// + 28 mov.b64 dup + 56 FFMA2. Crossbar delivery/SM drops 4x vs lane=channel.
__global__ __launch_bounds__(512, 1)
void gemm_kernel(float* __restrict__ y) {
    extern __shared__ float u_s[];       // [b=14][k=1152] = 64512B; then reduction buf

    const int a   = blockIdx.x;          // 0..13
    const int i0  = blockIdx.y * 32;
    const int tid = threadIdx.x;

    // ---- stage u_s[b][kj*384+kh*128+l] from g_U rows ap = a-1..a+1 ----
    float4* u4s = (float4*)u_s;
#pragma unroll
    for (int it = 0; it < 8; it++) {
        int idx = it * 512 + tid;                    // < 4096; valid < 4032
        if (idx < 4032) {
            int b  = idx / 288;                      // 1152/4
            int r  = idx - b * 288;
            int kj = r / 96;
            int r2 = r - kj * 96;                    // kh*32 + l4
            int ap = a - 1 + kj;
            float4 v = make_float4(0.f, 0.f, 0.f, 0.f);
            if (ap >= 0 && ap < 14)
                v = ((const float4*)g_U)[ap * 1344 + (r2 >> 5) * 448 + b * 32 + (r2 & 31)];
            u4s[b * 288 + r] = v;
        }
    }
    __syncthreads();

    const int warp = tid >> 5;           // 0..15
    const int lane = tid & 31;
    const int g = warp >> 1;             // channel quad 0..7
    const int s = warp & 1;              // K slice 0..1

    unsigned long long acc2[2][14];      // [cp][b]: lo=ch g*4+cp*2, hi=ch g*4+cp*2+1
#pragma unroll
    for (int cp = 0; cp < 2; cp++)
#pragma unroll
        for (int b = 0; b < 14; b++) acc2[cp][b] = 0ull;

    const ulonglong2* wp = ((const ulonglong2*)g_Wp)
        + (((s * 9) * 64 + (blockIdx.y * 8 + g)) * 32 + lane) * 2;
    const float* ub = u_s + s * 576 + lane * 2;

#pragma unroll 3
    for (int j = 0; j < 9; j++) {
        ulonglong2 wA = wp[j * 4096];                // (c0k0,c1k0 | c2k0,c3k0)
        ulonglong2 wB = wp[j * 4096 + 1];            // (c0k1,c1k1 | c2k1,c3k1)
        const float* uj = ub + j * 64;
#pragma unroll
        for (int b = 0; b < 14; b++) {
            float2 u2 = *(const float2*)(uj + b * 1152);   // LDS.64, conflict-free
            unsigned long long u00, u11;
            asm("mov.b64 %0, {%1, %1};" : "=l"(u00) : "f"(u2.x));
            asm("mov.b64 %0, {%1, %1};" : "=l"(u11) : "f"(u2.y));
            asm("fma.rn.f32x2 %0, %1, %2, %0;" : "+l"(acc2[0][b]) : "l"(wA.x), "l"(u00));
            asm("fma.rn.f32x2 %0, %1, %2, %0;" : "+l"(acc2[1][b]) : "l"(wA.y), "l"(u00));
            asm("fma.rn.f32x2 %0, %1, %2, %0;" : "+l"(acc2[0][b]) : "l"(wB.x), "l"(u11));
            asm("fma.rn.f32x2 %0, %1, %2, %0;" : "+l"(acc2[1][b]) : "l"(wB.y), "l"(u11));
        }
    }

    __syncthreads();                                 // u_s reusable as reduction buffer
    unsigned long long* red = (unsigned long long*)u_s;
    // red[((g*2+cp)*14 + b)*65 + s*32 + lane]  (stride 65 kills read-phase conflicts)
#pragma unroll
    for (int cp = 0; cp < 2; cp++)
#pragma unroll
        for (int b = 0; b < 14; b++)
            red[((g * 2 + cp) * 14 + b) * 65 + s * 32 + lane] = acc2[cp][b];
    __syncthreads();

    if (tid < 448) {
        int idx  = tid >> 1;             // (g*2+cp)*14 + b, 0..223
        int half = tid & 1;              // which channel of the pair
        const float* rf = (const float*)u_s + idx * 130 + half;
        float s0 = 0.f, s1 = 0.f, s2 = 0.f, s3 = 0.f;
#pragma unroll
        for (int q = 0; q < 64; q += 4) {
            s0 += rf[(q + 0) * 2];
            s1 += rf[(q + 1) * 2];
            s2 += rf[(q + 2) * 2];
            s3 += rf[(q + 3) * 2];
        }
        float sum = (s0 + s1) + (s2 + s3);
        int gcp = idx / 14;
        int b   = idx - gcp * 14;
        int ch  = i0 + (gcp >> 1) * 4 + (gcp & 1) * 2 + half;
        y[ch * 196 + a * 14 + b] = sum;
    }
}

extern "C" void kernel_launch(void* const* d_in, const int* in_sizes, int n_in,
                              void* d_out, int out_size) {
    const float* x = (const float*)d_in[0];
    const float* w = (const float*)d_in[1];
    float* y = (float*)d_out;

    cudaFuncSetAttribute(gemm_kernel,
                         cudaFuncAttributeMaxDynamicSharedMemorySize, GEMM_SMEM);

    prep_kernel<<<U_BLOCKS + W_BLOCKS, 256>>>(x, w);
    gemm_kernel<<<dim3(14, 8), 512, GEMM_SMEM>>>(y);
}

// round 15
// speedup vs baseline: 1.1775x; 1.1400x over previous
#include <cuda_runtime.h>
#include <cuda_bf16.h>

// y[i,a,b] = sum_{kj,kh,l} w[i,kj,kh,l] * U[a+kj-1, kh, b, l]   (zero pad on a+kj-1)
// U[ap,kh,b,l] = T(ap,kh,(b-1)%14, l+128) + T(ap,kh,b,l)
// T(ap,kh,b',c) = (0 <= b'+kh-1 < 14) ? x[c, ap, (b'+kh-2) mod 14] : 0
// Note: w natural k-linearization k = kj*384 + kh*128 + l matches u_s layout.

#define U_ELEMS (14 * 3 * 14 * 128)     // 75264
#define U_BLOCKS 294                     // 294*256 == 75264

__device__ float g_U[U_ELEMS];          // [ap][kh][b][l]

__global__ void prep_kernel(const float* __restrict__ x) {
    int e = blockIdx.x * 256 + threadIdx.x;          // < 75264
    int l  = e & 127;
    int b  = (e >> 7) % 14;
    int kh = (e / (128 * 14)) % 3;
    int ap = e / (128 * 14 * 3);

    float val = 0.0f;
    int t = b + kh - 1;
    if (t >= 0 && t < 14) {
        int wsrc = t - 1; if (wsrc < 0) wsrc += 14;
        val += x[l * 196 + ap * 14 + wsrc];
    }
    int bm = b - 1; if (bm < 0) bm += 14;
    int t1 = bm + kh - 1;
    if (t1 >= 0 && t1 < 14) {
        int wsrc = t1 - 1; if (wsrc < 0) wsrc += 14;
        val += x[(l + 128) * 196 + ap * 14 + wsrc];
    }
    g_U[e] = val;
}

// Grid (a=14, i-tile=8, b-half=2). Block 256 = 8 warps = 8 channel-quads, full K.
// Warp g: channels i0+g*4+{0..3}. Lane owns k = j*64 + lane*2 + {0,1}, j=0..17.
// k-parity f32x2 accumulation: LDG.64 w (natural layout, coalesced) and LDS.64 u
// pair (k,k+1) directly -> zero packing movs. acc2[4][7] = 56 regs.
// ~90 regs, 32KB smem -> 2 blocks/SM co-resident (224 blocks <= 296 slots).
__global__ __launch_bounds__(256)
void gemm_kernel(const float* __restrict__ w, float* __restrict__ y) {
    __shared__ float u_s[8064];          // [bb=7][k=1152] = 32256B; reused: red[224][33]

    const int a   = blockIdx.x;          // 0..13
    const int i0  = blockIdx.y * 32;
    const int h0  = blockIdx.z;          // b = h0*7 + bb
    const int tid = threadIdx.x;

    // ---- stage u_s[bb][kj*384+kh*128+l] from g_U rows ap = a-1..a+1 ----
    float4* u4s = (float4*)u_s;
#pragma unroll
    for (int it = 0; it < 8; it++) {
        int idx = it * 256 + tid;                    // < 2048; valid < 2016
        if (idx < 2016) {
            int bb = idx / 288;                      // 1152/4
            int r  = idx - bb * 288;
            int kj = r / 96;
            int r2 = r - kj * 96;                    // kh*32 + l4
            int ap = a - 1 + kj;
            float4 v = make_float4(0.f, 0.f, 0.f, 0.f);
            if (ap >= 0 && ap < 14)
                v = ((const float4*)g_U)[ap * 1344 + (r2 >> 5) * 448
                                         + (h0 * 7 + bb) * 32 + (r2 & 31)];
            u4s[bb * 288 + r] = v;
        }
    }
    __syncthreads();

    const int g    = tid >> 5;           // warp = channel quad 0..7
    const int lane = tid & 31;
    const int ch0  = i0 + g * 4;

    unsigned long long acc2[4][7];       // [c][bb]; lo = even-k partial, hi = odd-k
#pragma unroll
    for (int c = 0; c < 4; c++)
#pragma unroll
        for (int bb = 0; bb < 7; bb++) acc2[c][bb] = 0ull;

    // natural-layout w rows: 576 ull (k-pairs) per channel, coalesced LDG.64
    const unsigned long long* pw0 = (const unsigned long long*)w + (ch0 + 0) * 576 + lane;
    const unsigned long long* pw1 = (const unsigned long long*)w + (ch0 + 1) * 576 + lane;
    const unsigned long long* pw2 = (const unsigned long long*)w + (ch0 + 2) * 576 + lane;
    const unsigned long long* pw3 = (const unsigned long long*)w + (ch0 + 3) * 576 + lane;
    const unsigned long long* pu  = (const unsigned long long*)u_s + lane;

#pragma unroll 3
    for (int j = 0; j < 18; j++) {
        unsigned long long wv0 = pw0[j * 32];
        unsigned long long wv1 = pw1[j * 32];
        unsigned long long wv2 = pw2[j * 32];
        unsigned long long wv3 = pw3[j * 32];
#pragma unroll
        for (int bb = 0; bb < 7; bb++) {
            unsigned long long uv = pu[bb * 576 + j * 32];   // LDS.64, serves 4 ch
            asm("fma.rn.f32x2 %0, %1, %2, %0;" : "+l"(acc2[0][bb]) : "l"(wv0), "l"(uv));
            asm("fma.rn.f32x2 %0, %1, %2, %0;" : "+l"(acc2[1][bb]) : "l"(wv1), "l"(uv));
            asm("fma.rn.f32x2 %0, %1, %2, %0;" : "+l"(acc2[2][bb]) : "l"(wv2), "l"(uv));
            asm("fma.rn.f32x2 %0, %1, %2, %0;" : "+l"(acc2[3][bb]) : "l"(wv3), "l"(uv));
        }
    }

    __syncthreads();                                 // u_s reusable as red buffer
    float* red = u_s;                                // red[out][33], out = (g*4+c)*7+bb
#pragma unroll
    for (int c = 0; c < 4; c++)
#pragma unroll
        for (int bb = 0; bb < 7; bb++) {
            float lo, hi;
            asm("mov.b64 {%0, %1}, %2;" : "=f"(lo), "=f"(hi) : "l"(acc2[c][bb]));
            red[((g * 4 + c) * 7 + bb) * 33 + lane] = lo + hi;
        }
    __syncthreads();

    if (tid < 224) {
        const float* rf = red + tid * 33;
        float s0 = 0.f, s1 = 0.f, s2 = 0.f, s3 = 0.f;
#pragma unroll
        for (int q = 0; q < 32; q += 4) {
            s0 += rf[q + 0];
            s1 += rf[q + 1];
            s2 += rf[q + 2];
            s3 += rf[q + 3];
        }
        float sum = (s0 + s1) + (s2 + s3);
        int gc = tid / 7;                // g*4+c
        int bb = tid - gc * 7;
        y[(i0 + gc) * 196 + a * 14 + h0 * 7 + bb] = sum;
    }
}

extern "C" void kernel_launch(void* const* d_in, const int* in_sizes, int n_in,
                              void* d_out, int out_size) {
    const float* x = (const float*)d_in[0];
    const float* w = (const float*)d_in[1];
    float* y = (float*)d_out;

    prep_kernel<<<U_BLOCKS, 256>>>(x);
    gemm_kernel<<<dim3(14, 8, 2), 256>>>(w, y);
}